// round 5
// baseline (speedup 1.0000x reference)
#include <cuda_runtime.h>
#include <math.h>

#define T_DATA 40000
#define SUB    32
#define EE     2000
#define EI     400
#define TAPS   200
#define NCOS   17
#define CBT    2048   // conv tile (outputs per block), 256 thr * 8
#define VBT    512    // vconv tile

// padded smem index: +1 float2 per 8 -> per-thread stride 9 float2 (odd) ->
// lane bank-pair 9*i mod 16 is a bijection -> conflict-free LDS.64
#define PX(i) ((i) + ((i) >> 3))

// ---------------- device scratch (no allocations allowed) ----------------
__device__ float  g_syn_e[SUB * T_DATA];
__device__ float  g_syn_i[SUB * T_DATA];
__device__ float  g_syn[(SUB + 1) * T_DATA];   // ch 0..31 subunit drive, ch 32 = hist_filt
__device__ float  g_zout[T_DATA];
__device__ float  g_ek[SUB * TAPS];
__device__ float  g_ik[SUB * TAPS];
__device__ float  g_hk[TAPS];
__device__ float  g_ok[TAPS];
__device__ int    g_chn[SUB * 2];              // up to 2 children per node (binary tree)
__device__ float  g_chw[SUB * 2];
__device__ float2 g_lut_e[EE];                 // (weight, bitcast subunit)
__device__ float2 g_lut_i[EI];

// ---------------- f32x2 helpers (sm_103a packed fp32) ----------------
__device__ __forceinline__ unsigned long long pk2(float2 v) {
    unsigned long long r;
    asm("mov.b64 %0, {%1, %2};" : "=l"(r) : "f"(v.x), "f"(v.y));
    return r;
}
__device__ __forceinline__ void fma2(unsigned long long& d, unsigned long long a,
                                     unsigned long long b) {
    asm("fma.rn.f32x2 %0, %1, %2, %0;" : "+l"(d) : "l"(a), "l"(b));
}
__device__ __forceinline__ float unpk_sum(unsigned long long v) {
    float lo, hi;
    asm("mov.b64 {%0, %1}, %2;" : "=f"(lo), "=f"(hi) : "l"(v));
    return lo + hi;
}

// branchless fast tanh: MUFU EX2 + MUFU RCP, no libm branches.
// |err| ~1e-6 abs, far inside the 1e-3 gate.
__device__ __forceinline__ float tanh_b(float x) {
    float e = __expf(-2.0f * fabsf(x));
    float r = __fdividef(1.0f - e, 1.0f + e);
    return copysignf(r, x);
}

// ---------------- K0: prep (grid-parallel) ----------------
__global__ void prep_kernel(const float* __restrict__ C_den,
                            const float* __restrict__ Cse,
                            const float* __restrict__ Csi,
                            const float* __restrict__ Tau,
                            const float* __restrict__ Delta,
                            const float* __restrict__ Wsyn,
                            const float* __restrict__ Wsub,
                            const float* __restrict__ Whist,
                            const float* __restrict__ TauOut,
                            const float* __restrict__ Wout,
                            float* __restrict__ d_out, int out_size) {
    const int gtid = blockIdx.x * blockDim.x + threadIdx.x;
    const int gsz  = gridDim.x * blockDim.x;

    // one-hot column -> (subunit, weight)
    for (int e = gtid; e < EE; e += gsz) {
        int s0 = 0; float w = 0.f;
        #pragma unroll 8
        for (int s = 0; s < SUB; s++) {
            float c = Cse[s * EE + e];
            if (c != 0.f) { s0 = s; w = c; }
        }
        g_lut_e[e] = make_float2(w, __int_as_float(s0));
    }
    for (int e = gtid; e < EI; e += gsz) {
        int s0 = 0; float w = 0.f;
        #pragma unroll 8
        for (int s = 0; s < SUB; s++) {
            float c = Csi[s * EI + e];
            if (c != 0.f) { s0 = s; w = c; }
        }
        g_lut_i[e] = make_float2(w, __int_as_float(s0));
    }

    // alpha kernels (e/i) + out_filters rows
    for (int idx = gtid; idx < SUB * TAPS; idx += gsz) {
        const int s = idx / TAPS, u = idx % TAPS;
        const float tf = (float)u;
        float te  = fmaxf(tf - expf(Delta[s * 2 + 0]), 0.f);
        float tte = te / expf(Tau[s * 2 + 0]);
        float ek  = tte * expf(-tte) * expf(Wsyn[s * 2 + 0]);
        float ti  = fmaxf(tf - expf(Delta[s * 2 + 1]), 0.f);
        float tti = ti / expf(Tau[s * 2 + 1]);
        float ik  = -tti * expf(-tti) * expf(Wsyn[s * 2 + 1]);
        g_ek[idx] = ek;
        g_ik[idx] = ik;
        const int base = 2 * T_DATA;
        if (base + idx < out_size)              d_out[base + idx] = ek;
        if (base + SUB * TAPS + idx < out_size) d_out[base + SUB * TAPS + idx] = ik;
    }

    // history kernel from raised-cosine basis
    for (int u = gtid; u < TAPS; u += gsz) {
        const float raw = 4.0f * logf((float)u + 1.0f);
        const float pi_f    = 3.14159274101257324f;
        const float half_pi = 1.57079637050628662f;
        float hk = 0.f;
        for (int n = 0; n < NCOS; n++) {
            float phi = half_pi * (float)n;
            float b = 0.f;
            if (raw >= phi - pi_f && raw <= phi + pi_f)
                b = 0.5f * cosf(raw - phi) + 0.5f;
            hk -= expf(Whist[n]) * b;
        }
        g_hk[u] = hk;
        const int base = 2 * T_DATA + 2 * SUB * TAPS;
        if (base + u < out_size) d_out[base + u] = hk;
    }

    // output alpha kernel
    for (int u = gtid; u < TAPS; u += gsz) {
        float tto = (float)u / expf(TauOut[0]);
        g_ok[u] = tto * expf(-tto) * expf(Wout[0]);
    }

    // per-node children (binary dendrite tree: <=2 children, larger index);
    // reads C_den / Wsub directly -> no dependency on other tasks
    if (gtid < SUB) {
        const int i = gtid;
        int c0 = 0, c1 = 0; float w0 = 0.f, w1 = 0.f; int cnt = 0;
        for (int j = i + 1; j < SUB; j++) {
            float c = C_den[i * SUB + j];
            if (c != 0.f) {
                float w = c * expf(Wsub[j]);
                if (cnt == 0) { c0 = j; w0 = w; }
                else          { c1 = j; w1 = w; }
                cnt++;
            }
        }
        g_chn[i * 2 + 0] = c0;  g_chw[i * 2 + 0] = w0;
        g_chn[i * 2 + 1] = c1;  g_chw[i * 2 + 1] = w1;
    }
}

// ---------------- K1: spike projection  S @ Csyn^T  (one-hot scatter) ----------------
#define PBT 16  // timesteps per block
__global__ void proj_kernel(const float* __restrict__ Se, const float* __restrict__ Si) {
    __shared__ float acc_e[PBT][SUB + 1];
    __shared__ float acc_i[PBT][SUB + 1];
    const int tid = threadIdx.x;
    for (int i = tid; i < PBT * (SUB + 1); i += 256) {
        (&acc_e[0][0])[i] = 0.f;
        (&acc_i[0][0])[i] = 0.f;
    }
    __syncthreads();

    const int t0 = blockIdx.x * PBT;
    const float4* Se4 = reinterpret_cast<const float4*>(Se);
    const float4* Si4 = reinterpret_cast<const float4*>(Si);

    const int EROW = EE / 4;  // 500
    #pragma unroll 4
    for (int idx = tid; idx < PBT * EROW; idx += 256) {
        const int tl = idx / EROW, c4 = idx % EROW;
        const float4 v = Se4[(size_t)(t0 + tl) * EROW + c4];
        if (v.x != 0.f) { float2 p = g_lut_e[c4 * 4 + 0]; atomicAdd(&acc_e[tl][__float_as_int(p.y)], v.x * p.x); }
        if (v.y != 0.f) { float2 p = g_lut_e[c4 * 4 + 1]; atomicAdd(&acc_e[tl][__float_as_int(p.y)], v.y * p.x); }
        if (v.z != 0.f) { float2 p = g_lut_e[c4 * 4 + 2]; atomicAdd(&acc_e[tl][__float_as_int(p.y)], v.z * p.x); }
        if (v.w != 0.f) { float2 p = g_lut_e[c4 * 4 + 3]; atomicAdd(&acc_e[tl][__float_as_int(p.y)], v.w * p.x); }
    }
    const int IROW = EI / 4;  // 100
    #pragma unroll 4
    for (int idx = tid; idx < PBT * IROW; idx += 256) {
        const int tl = idx / IROW, c4 = idx % IROW;
        const float4 v = Si4[(size_t)(t0 + tl) * IROW + c4];
        if (v.x != 0.f) { float2 p = g_lut_i[c4 * 4 + 0]; atomicAdd(&acc_i[tl][__float_as_int(p.y)], v.x * p.x); }
        if (v.y != 0.f) { float2 p = g_lut_i[c4 * 4 + 1]; atomicAdd(&acc_i[tl][__float_as_int(p.y)], v.y * p.x); }
        if (v.z != 0.f) { float2 p = g_lut_i[c4 * 4 + 2]; atomicAdd(&acc_i[tl][__float_as_int(p.y)], v.z * p.x); }
        if (v.w != 0.f) { float2 p = g_lut_i[c4 * 4 + 3]; atomicAdd(&acc_i[tl][__float_as_int(p.y)], v.w * p.x); }
    }
    __syncthreads();

    for (int idx = tid; idx < SUB * PBT; idx += 256) {
        const int s = idx / PBT, tl = idx % PBT;
        g_syn_e[s * T_DATA + t0 + tl] = acc_e[tl][s];
        g_syn_i[s * T_DATA + t0 + tl] = acc_i[tl][s];
    }
}

// ---------------- K2: 33-ch 200-tap causal conv (f32x2 packed, padded smem) ----------
__global__ void conv_kernel(const float* __restrict__ Z) {
    __shared__ float2 sig[PX(CBT + TAPS - 1) + 2];
    __shared__ float2 kk[TAPS];
    const int ch  = blockIdx.y;
    const int t0  = blockIdx.x * CBT;
    const int tid = threadIdx.x;
    const bool has_i = (ch < SUB);

    const float* pe = has_i ? (g_syn_e + ch * T_DATA) : Z;
    const float* pi = has_i ? (g_syn_i + ch * T_DATA) : nullptr;
    const float* ke = has_i ? (g_ek + ch * TAPS) : g_hk;
    const float* ki = has_i ? (g_ik + ch * TAPS) : nullptr;

    for (int i = tid; i < CBT + TAPS; i += 256) {
        const int t = t0 - TAPS + i;
        const bool ok = (t >= 0) && (t < T_DATA);
        float a = ok ? pe[t] : 0.f;
        float b = (ok && has_i) ? pi[t] : 0.f;
        sig[PX(i)] = make_float2(a, b);
    }
    for (int u = tid; u < TAPS; u += 256)
        kk[u] = make_float2(ke[u], has_i ? ki[u] : 0.f);
    __syncthreads();

    const int base = tid * 8;  // first output (tile-local)
    unsigned long long acc[8];
    unsigned long long w[8];
    #pragma unroll
    for (int r = 0; r < 8; r++) acc[r] = 0ull;
    #pragma unroll
    for (int r = 0; r < 8; r++) w[(7 + r) & 7] = pk2(sig[PX(base + 199 + r)]);

    for (int g = 0; g < TAPS; g += 8) {
        #pragma unroll
        for (int c = 0; c < 8; c++) {
            const int u = g + c;
            if (u > 0) w[(7 - c) & 7] = pk2(sig[PX(base + 199 - u)]);
            const unsigned long long k2 = pk2(kk[u]);
            #pragma unroll
            for (int r = 0; r < 8; r++)
                fma2(acc[r], k2, w[(7 - c + r) & 7]);
        }
    }

    #pragma unroll
    for (int r = 0; r < 8; r++) {
        const int t = t0 + base + r;
        if (t < T_DATA) g_syn[ch * T_DATA + t] = unpk_sum(acc[r]);
    }
}

// ---------------- K3: tree walk, level-parallel, fast tanh -------------
__global__ void tree_kernel(const float* __restrict__ Theta,
                            float* __restrict__ d_out, int out_size) {
    __shared__ float th[SUB];
    __shared__ int   chn[SUB * 2];
    __shared__ float chw[SUB * 2];
    const int tid = threadIdx.x;
    if (tid < SUB) th[tid] = Theta[tid];
    if (tid < SUB * 2) { chn[tid] = g_chn[tid]; chw[tid] = g_chw[tid]; }
    __syncthreads();

    const int t = blockIdx.x * 256 + tid;
    if (t >= T_DATA) return;

    float v[SUB];
    float hist = g_syn[SUB * T_DATA + t];
    #pragma unroll
    for (int s = 0; s < SUB; s++) v[s] = g_syn[s * T_DATA + t];

    // level batches [16,31] -> [8,15] -> [4,7] -> [2,3] -> [1]
    #define TSTEP(idx)                                                        \
        v[idx] = tanh_b(fmaf(chw[2*(idx)+1], v[chn[2*(idx)+1]],               \
                        fmaf(chw[2*(idx)],   v[chn[2*(idx)]],                 \
                             v[idx] + th[idx])));
    #pragma unroll
    for (int i = 16; i < 32; i++) TSTEP(i)
    #pragma unroll
    for (int i = 8; i < 16; i++) TSTEP(i)
    #pragma unroll
    for (int i = 4; i < 8; i++) TSTEP(i)
    #pragma unroll
    for (int i = 2; i < 4; i++) TSTEP(i)
    TSTEP(1)
    #undef TSTEP

    float zin = hist + v[0] + th[0];
    zin = fmaf(chw[0], v[chn[0]], zin);
    zin = fmaf(chw[1], v[chn[1]], zin);

    const float zo = (zin > 0.f) ? 1.f : 0.f;
    g_zout[t] = zo;
    if (T_DATA + t < out_size) d_out[T_DATA + t] = zo;
}

// ---------------- K4: output alpha-kernel conv of Z_out -> V_out ------------------
__global__ void vconv_kernel(float* __restrict__ d_out, int out_size) {
    __shared__ float sig[VBT + TAPS];
    __shared__ float kern[TAPS];
    const int t0  = blockIdx.x * VBT;
    const int tid = threadIdx.x;
    for (int i = tid; i < VBT + TAPS; i += 256) {
        const int t = t0 - TAPS + i;
        sig[i] = (t >= 0 && t < T_DATA) ? g_zout[t] : 0.f;
    }
    for (int u = tid; u < TAPS; u += 256) kern[u] = g_ok[u];
    __syncthreads();

    float a0 = 0.f, a1 = 0.f;
    for (int u = 0; u < TAPS; u++) {
        const float k = kern[u];
        a0 = fmaf(k, sig[tid + 199 - u], a0);
        a1 = fmaf(k, sig[tid + 256 + 199 - u], a1);
    }
    int t = t0 + tid;
    if (t < T_DATA && t < out_size) d_out[t] = a0;
    t += 256;
    if (t < T_DATA && t < out_size) d_out[t] = a1;
}

// ---------------- launch ----------------
extern "C" void kernel_launch(void* const* d_in, const int* in_sizes, int n_in,
                              void* d_out, int out_size) {
    const float* S_e    = (const float*)d_in[0];
    const float* S_i    = (const float*)d_in[1];
    const float* Z      = (const float*)d_in[2];
    const float* C_den  = (const float*)d_in[3];
    const float* Cse    = (const float*)d_in[4];
    const float* Csi    = (const float*)d_in[5];
    const float* Tau    = (const float*)d_in[6];
    const float* Delta  = (const float*)d_in[7];
    const float* Wsyn   = (const float*)d_in[8];
    const float* Wsub   = (const float*)d_in[9];
    const float* Whist  = (const float*)d_in[10];
    const float* Theta  = (const float*)d_in[11];
    const float* TauOut = (const float*)d_in[12];
    const float* Wout   = (const float*)d_in[13];
    float* out = (float*)d_out;

    prep_kernel<<<96, 256>>>(C_den, Cse, Csi, Tau, Delta, Wsyn, Wsub, Whist,
                             TauOut, Wout, out, out_size);
    proj_kernel<<<T_DATA / PBT, 256>>>(S_e, S_i);
    const int ctiles = (T_DATA + CBT - 1) / CBT;  // 20
    conv_kernel<<<dim3(ctiles, SUB + 1), 256>>>(Z);
    tree_kernel<<<(T_DATA + 255) / 256, 256>>>(Theta, out, out_size);
    vconv_kernel<<<(T_DATA + VBT - 1) / VBT, 256>>>(out, out_size);
}

// round 7
// speedup vs baseline: 1.3228x; 1.3228x over previous
#include <cuda_runtime.h>
#include <math.h>

#define T_DATA 40000
#define SUB    32
#define EE     2000
#define EI     400
#define TAPS   200
#define NCOS   17
#define CBT    2048   // conv tile (outputs per block), 256 thr * 8
#define VBT    512    // vconv tile

// padded smem index: +1 float2 per 8 -> per-thread stride 9 float2 (odd) ->
// conflict-free LDS.64
#define PX(i) ((i) + ((i) >> 3))

// ---------------- device scratch (no allocations allowed) ----------------
__device__ float  g_syn_e[SUB * T_DATA];
__device__ float  g_syn_i[SUB * T_DATA];
__device__ float  g_syn[(SUB + 1) * T_DATA];   // ch 0..31 subunit drive, ch 32 = hist_filt
__device__ float  g_zout[T_DATA];
__device__ float  g_ek[SUB * TAPS];
__device__ float  g_ik[SUB * TAPS];
__device__ float  g_hk[TAPS];
__device__ float  g_ok[TAPS];
__device__ int    g_chn[SUB * 2];              // up to 2 children per node (binary tree)
__device__ float  g_chw[SUB * 2];
__device__ float2 g_lut_e[EE];                 // (weight, bitcast subunit)
__device__ float2 g_lut_i[EI];

// ---------------- f32x2 helpers (sm_103a packed fp32) ----------------
__device__ __forceinline__ unsigned long long pk2(float2 v) {
    unsigned long long r;
    asm("mov.b64 %0, {%1, %2};" : "=l"(r) : "f"(v.x), "f"(v.y));
    return r;
}
__device__ __forceinline__ void fma2(unsigned long long& d, unsigned long long a,
                                     unsigned long long b) {
    asm("fma.rn.f32x2 %0, %1, %2, %0;" : "+l"(d) : "l"(a), "l"(b));
}
__device__ __forceinline__ float unpk_sum(unsigned long long v) {
    float lo, hi;
    asm("mov.b64 {%0, %1}, %2;" : "=f"(lo), "=f"(hi) : "l"(v));
    return lo + hi;
}

// branchless fast tanh: MUFU EX2 + MUFU RCP, no libm branches. |err| ~1e-6.
__device__ __forceinline__ float tanh_b(float x) {
    float e = __expf(-2.0f * fabsf(x));
    float r = __fdividef(1.0f - e, 1.0f + e);
    return copysignf(r, x);
}

// ---------------- K0: prep (grid-parallel) ----------------
__global__ void prep_kernel(const float* __restrict__ C_den,
                            const float* __restrict__ Cse,
                            const float* __restrict__ Csi,
                            const float* __restrict__ Tau,
                            const float* __restrict__ Delta,
                            const float* __restrict__ Wsyn,
                            const float* __restrict__ Wsub,
                            const float* __restrict__ Whist,
                            const float* __restrict__ TauOut,
                            const float* __restrict__ Wout,
                            float* __restrict__ d_out, int out_size) {
    const int gtid = blockIdx.x * blockDim.x + threadIdx.x;
    const int gsz  = gridDim.x * blockDim.x;

    // one-hot column -> (subunit, weight)
    for (int e = gtid; e < EE; e += gsz) {
        int s0 = 0; float w = 0.f;
        for (int s = 0; s < SUB; s++) {
            float c = Cse[s * EE + e];
            if (c != 0.f) { s0 = s; w = c; }
        }
        g_lut_e[e] = make_float2(w, __int_as_float(s0));
    }
    for (int e = gtid; e < EI; e += gsz) {
        int s0 = 0; float w = 0.f;
        for (int s = 0; s < SUB; s++) {
            float c = Csi[s * EI + e];
            if (c != 0.f) { s0 = s; w = c; }
        }
        g_lut_i[e] = make_float2(w, __int_as_float(s0));
    }

    // alpha kernels (e/i) + out_filters rows
    for (int idx = gtid; idx < SUB * TAPS; idx += gsz) {
        const int s = idx / TAPS, u = idx % TAPS;
        const float tf = (float)u;
        float te  = fmaxf(tf - expf(Delta[s * 2 + 0]), 0.f);
        float tte = te / expf(Tau[s * 2 + 0]);
        float ek  = tte * expf(-tte) * expf(Wsyn[s * 2 + 0]);
        float ti  = fmaxf(tf - expf(Delta[s * 2 + 1]), 0.f);
        float tti = ti / expf(Tau[s * 2 + 1]);
        float ik  = -tti * expf(-tti) * expf(Wsyn[s * 2 + 1]);
        g_ek[idx] = ek;
        g_ik[idx] = ik;
        const int base = 2 * T_DATA;
        if (base + idx < out_size)              d_out[base + idx] = ek;
        if (base + SUB * TAPS + idx < out_size) d_out[base + SUB * TAPS + idx] = ik;
    }

    // history kernel from raised-cosine basis
    for (int u = gtid; u < TAPS; u += gsz) {
        const float raw = 4.0f * logf((float)u + 1.0f);
        const float pi_f    = 3.14159274101257324f;
        const float half_pi = 1.57079637050628662f;
        float hk = 0.f;
        for (int n = 0; n < NCOS; n++) {
            float phi = half_pi * (float)n;
            float b = 0.f;
            if (raw >= phi - pi_f && raw <= phi + pi_f)
                b = 0.5f * cosf(raw - phi) + 0.5f;
            hk -= expf(Whist[n]) * b;
        }
        g_hk[u] = hk;
        const int base = 2 * T_DATA + 2 * SUB * TAPS;
        if (base + u < out_size) d_out[base + u] = hk;
    }

    // output alpha kernel
    for (int u = gtid; u < TAPS; u += gsz) {
        float tto = (float)u / expf(TauOut[0]);
        g_ok[u] = tto * expf(-tto) * expf(Wout[0]);
    }

    // per-node children (binary dendrite tree: <=2 children, larger index)
    if (gtid < SUB) {
        const int i = gtid;
        int c0 = 0, c1 = 0; float w0 = 0.f, w1 = 0.f; int cnt = 0;
        for (int j = i + 1; j < SUB; j++) {
            float c = C_den[i * SUB + j];
            if (c != 0.f) {
                float w = c * expf(Wsub[j]);
                if (cnt == 0) { c0 = j; w0 = w; }
                else          { c1 = j; w1 = w; }
                cnt++;
            }
        }
        g_chn[i * 2 + 0] = c0;  g_chw[i * 2 + 0] = w0;
        g_chn[i * 2 + 1] = c1;  g_chw[i * 2 + 1] = w1;
    }
}

// ---------------- K1: spike projection (warp-per-row, no div/mod) ----------------
#define PBT 16  // timesteps per block
__global__ void proj_kernel(const float* __restrict__ Se, const float* __restrict__ Si) {
    __shared__ float acc_e[PBT][SUB + 1];
    __shared__ float acc_i[PBT][SUB + 1];
    const int tid  = threadIdx.x;
    const int wid  = tid >> 5;
    const int lane = tid & 31;
    for (int i = tid; i < PBT * (SUB + 1); i += 256) {
        (&acc_e[0][0])[i] = 0.f;
        (&acc_i[0][0])[i] = 0.f;
    }
    __syncthreads();

    const int t0 = blockIdx.x * PBT;
    const float4* Se4 = reinterpret_cast<const float4*>(Se);
    const float4* Si4 = reinterpret_cast<const float4*>(Si);
    const int EROW = EE / 4;  // 500
    const int IROW = EI / 4;  // 100

    // 8 warps, 16 rows -> 2 rows per warp; lanes stride the row (coalesced 512B)
    #pragma unroll
    for (int rr = 0; rr < 2; rr++) {
        const int tl = wid * 2 + rr;
        const float4* rowE = Se4 + (size_t)(t0 + tl) * EROW;
        float* accE = acc_e[tl];
        #pragma unroll 4
        for (int c4 = lane; c4 < EROW; c4 += 32) {
            const float4 v = rowE[c4];
            if (v.x != 0.f) { float2 p = g_lut_e[c4 * 4 + 0]; atomicAdd(&accE[__float_as_int(p.y)], v.x * p.x); }
            if (v.y != 0.f) { float2 p = g_lut_e[c4 * 4 + 1]; atomicAdd(&accE[__float_as_int(p.y)], v.y * p.x); }
            if (v.z != 0.f) { float2 p = g_lut_e[c4 * 4 + 2]; atomicAdd(&accE[__float_as_int(p.y)], v.z * p.x); }
            if (v.w != 0.f) { float2 p = g_lut_e[c4 * 4 + 3]; atomicAdd(&accE[__float_as_int(p.y)], v.w * p.x); }
        }
        const float4* rowI = Si4 + (size_t)(t0 + tl) * IROW;
        float* accI = acc_i[tl];
        #pragma unroll
        for (int c4 = lane; c4 < IROW; c4 += 32) {
            const float4 v = rowI[c4];
            if (v.x != 0.f) { float2 p = g_lut_i[c4 * 4 + 0]; atomicAdd(&accI[__float_as_int(p.y)], v.x * p.x); }
            if (v.y != 0.f) { float2 p = g_lut_i[c4 * 4 + 1]; atomicAdd(&accI[__float_as_int(p.y)], v.y * p.x); }
            if (v.z != 0.f) { float2 p = g_lut_i[c4 * 4 + 2]; atomicAdd(&accI[__float_as_int(p.y)], v.z * p.x); }
            if (v.w != 0.f) { float2 p = g_lut_i[c4 * 4 + 3]; atomicAdd(&accI[__float_as_int(p.y)], v.w * p.x); }
        }
    }
    __syncthreads();

    for (int idx = tid; idx < SUB * PBT; idx += 256) {
        const int s = idx / PBT, tl = idx % PBT;
        g_syn_e[s * T_DATA + t0 + tl] = acc_e[tl][s];
        g_syn_i[s * T_DATA + t0 + tl] = acc_i[tl][s];
    }
}

// ---------------- K2: 33-ch 200-tap causal conv (f32x2 packed, padded smem) ----------
__global__ void conv_kernel(const float* __restrict__ Z) {
    __shared__ float2 sig[PX(CBT + TAPS - 1) + 2];
    __shared__ float2 kk[TAPS];
    const int ch  = blockIdx.y;
    const int t0  = blockIdx.x * CBT;
    const int tid = threadIdx.x;
    const bool has_i = (ch < SUB);

    const float* pe = has_i ? (g_syn_e + ch * T_DATA) : Z;
    const float* pi = has_i ? (g_syn_i + ch * T_DATA) : nullptr;
    const float* ke = has_i ? (g_ek + ch * TAPS) : g_hk;
    const float* ki = has_i ? (g_ik + ch * TAPS) : nullptr;

    for (int i = tid; i < CBT + TAPS; i += 256) {
        const int t = t0 - TAPS + i;
        const bool ok = (t >= 0) && (t < T_DATA);
        float a = ok ? pe[t] : 0.f;
        float b = (ok && has_i) ? pi[t] : 0.f;
        sig[PX(i)] = make_float2(a, b);
    }
    for (int u = tid; u < TAPS; u += 256)
        kk[u] = make_float2(ke[u], has_i ? ki[u] : 0.f);
    __syncthreads();

    const int base = tid * 8;
    unsigned long long acc[8];
    unsigned long long w[8];
    #pragma unroll
    for (int r = 0; r < 8; r++) acc[r] = 0ull;
    #pragma unroll
    for (int r = 0; r < 8; r++) w[(7 + r) & 7] = pk2(sig[PX(base + 199 + r)]);

    for (int g = 0; g < TAPS; g += 8) {
        #pragma unroll
        for (int c = 0; c < 8; c++) {
            const int u = g + c;
            if (u > 0) w[(7 - c) & 7] = pk2(sig[PX(base + 199 - u)]);
            const unsigned long long k2 = pk2(kk[u]);
            #pragma unroll
            for (int r = 0; r < 8; r++)
                fma2(acc[r], k2, w[(7 - c + r) & 7]);
        }
    }

    #pragma unroll
    for (int r = 0; r < 8; r++) {
        const int t = t0 + base + r;
        if (t < T_DATA) g_syn[ch * T_DATA + t] = unpk_sum(acc[r]);
    }
}

// ---------------- K3: tree walk, 2 timesteps/thread (79 blocks = 0.53 waves) --------
__global__ void tree_kernel(const float* __restrict__ Theta,
                            float* __restrict__ d_out, int out_size) {
    __shared__ float th[SUB];
    __shared__ int   chn[SUB * 2];
    __shared__ float chw[SUB * 2];
    const int tid = threadIdx.x;
    if (tid < SUB) th[tid] = Theta[tid];
    if (tid < SUB * 2) { chn[tid] = g_chn[tid]; chw[tid] = g_chw[tid]; }
    __syncthreads();

    const int gid = blockIdx.x * 256 + tid;   // pair index
    const int t0  = gid * 2;
    if (t0 >= T_DATA) return;

    // float2 loads: both samples of a channel in one LDG.64 (t0 even -> aligned)
    float2 v[SUB + 1];
    const float2* syn2 = reinterpret_cast<const float2*>(g_syn);
    #pragma unroll
    for (int s = 0; s <= SUB; s++) v[s] = syn2[s * (T_DATA / 2) + gid];

    // level batches [16,31] -> [8,15] -> [4,7] -> [2,3] -> [1]; the two
    // samples interleave inside each level for 2x ILP on the MUFU chains.
    #define TSTEP(idx) {                                                      \
        const int   c0 = chn[2*(idx)],   c1 = chn[2*(idx)+1];                 \
        const float w0 = chw[2*(idx)],   w1 = chw[2*(idx)+1];                 \
        float a0 = v[idx].x + th[idx];                                        \
        float a1 = v[idx].y + th[idx];                                        \
        a0 = fmaf(w0, v[c0].x, a0); a1 = fmaf(w0, v[c0].y, a1);               \
        a0 = fmaf(w1, v[c1].x, a0); a1 = fmaf(w1, v[c1].y, a1);               \
        v[idx].x = tanh_b(a0);      v[idx].y = tanh_b(a1); }
    #pragma unroll
    for (int i = 16; i < 32; i++) TSTEP(i)
    #pragma unroll
    for (int i = 8; i < 16; i++) TSTEP(i)
    #pragma unroll
    for (int i = 4; i < 8; i++) TSTEP(i)
    #pragma unroll
    for (int i = 2; i < 4; i++) TSTEP(i)
    TSTEP(1)
    #undef TSTEP

    const int   c0 = chn[0],  c1 = chn[1];
    const float w0 = chw[0],  w1 = chw[1];
    float z0 = v[SUB].x + v[0].x + th[0];   // hist + syn[:,0] + Theta[0]
    float z1 = v[SUB].y + v[0].y + th[0];
    z0 = fmaf(w0, v[c0].x, z0); z1 = fmaf(w0, v[c0].y, z1);
    z0 = fmaf(w1, v[c1].x, z0); z1 = fmaf(w1, v[c1].y, z1);

    float2 zo = make_float2(z0 > 0.f ? 1.f : 0.f, z1 > 0.f ? 1.f : 0.f);
    reinterpret_cast<float2*>(g_zout)[gid] = zo;
    if (T_DATA + t0     < out_size) d_out[T_DATA + t0]     = zo.x;
    if (T_DATA + t0 + 1 < out_size) d_out[T_DATA + t0 + 1] = zo.y;
}

// ---------------- K4: output alpha-kernel conv of Z_out -> V_out ------------------
__global__ void vconv_kernel(float* __restrict__ d_out, int out_size) {
    __shared__ float sig[VBT + TAPS];
    __shared__ float kern[TAPS];
    const int t0  = blockIdx.x * VBT;
    const int tid = threadIdx.x;
    for (int i = tid; i < VBT + TAPS; i += 256) {
        const int t = t0 - TAPS + i;
        sig[i] = (t >= 0 && t < T_DATA) ? g_zout[t] : 0.f;
    }
    for (int u = tid; u < TAPS; u += 256) kern[u] = g_ok[u];
    __syncthreads();

    float a0 = 0.f, a1 = 0.f;
    for (int u = 0; u < TAPS; u++) {
        const float k = kern[u];
        a0 = fmaf(k, sig[tid + 199 - u], a0);
        a1 = fmaf(k, sig[tid + 256 + 199 - u], a1);
    }
    int t = t0 + tid;
    if (t < T_DATA && t < out_size) d_out[t] = a0;
    t += 256;
    if (t < T_DATA && t < out_size) d_out[t] = a1;
}

// ---------------- launch ----------------
extern "C" void kernel_launch(void* const* d_in, const int* in_sizes, int n_in,
                              void* d_out, int out_size) {
    const float* S_e    = (const float*)d_in[0];
    const float* S_i    = (const float*)d_in[1];
    const float* Z      = (const float*)d_in[2];
    const float* C_den  = (const float*)d_in[3];
    const float* Cse    = (const float*)d_in[4];
    const float* Csi    = (const float*)d_in[5];
    const float* Tau    = (const float*)d_in[6];
    const float* Delta  = (const float*)d_in[7];
    const float* Wsyn   = (const float*)d_in[8];
    const float* Wsub   = (const float*)d_in[9];
    const float* Whist  = (const float*)d_in[10];
    const float* Theta  = (const float*)d_in[11];
    const float* TauOut = (const float*)d_in[12];
    const float* Wout   = (const float*)d_in[13];
    float* out = (float*)d_out;

    prep_kernel<<<64, 256>>>(C_den, Cse, Csi, Tau, Delta, Wsyn, Wsub, Whist,
                             TauOut, Wout, out, out_size);
    proj_kernel<<<T_DATA / PBT, 256>>>(S_e, S_i);
    const int ctiles = (T_DATA + CBT - 1) / CBT;  // 20
    conv_kernel<<<dim3(ctiles, SUB + 1), 256>>>(Z);
    tree_kernel<<<(T_DATA / 2 + 255) / 256, 256>>>(Theta, out, out_size);  // 79 blocks
    vconv_kernel<<<(T_DATA + VBT - 1) / VBT, 256>>>(out, out_size);
}

// round 8
// speedup vs baseline: 1.3775x; 1.0414x over previous
#include <cuda_runtime.h>
#include <math.h>

#define T_DATA 40000
#define SUB    32
#define EE     2000
#define EI     400
#define TAPS   200
#define NCOS   17
#define CBT    2048   // conv tile (outputs per block), 256 thr * 8
#define VBT    512    // vconv tile

// padded smem index: +1 float2 per 8 -> per-thread stride 9 float2 (odd) ->
// conflict-free LDS.64
#define PX(i) ((i) + ((i) >> 3))

// ---------------- device scratch (no allocations allowed) ----------------
__device__ float  g_syn_e[SUB * T_DATA];
__device__ float  g_syn_i[SUB * T_DATA];
__device__ float  g_syn[(SUB + 1) * T_DATA];   // ch 0..31 subunit drive, ch 32 = hist_filt
__device__ float  g_zout[T_DATA];
__device__ float  g_ek[SUB * TAPS];
__device__ float  g_ik[SUB * TAPS];
__device__ float  g_hk[TAPS];
__device__ float  g_ok[TAPS];
__device__ int    g_ntap[SUB + 1];             // adaptive per-channel tap count (mult of 8)
__device__ int    g_chn[SUB * 2];              // up to 2 children per node (binary tree)
__device__ float  g_chw[SUB * 2];
__device__ float2 g_lut_e[EE];                 // (weight, bitcast subunit)
__device__ float2 g_lut_i[EI];

// ---------------- f32x2 helpers (sm_103a packed fp32) ----------------
__device__ __forceinline__ unsigned long long pk2(float2 v) {
    unsigned long long r;
    asm("mov.b64 %0, {%1, %2};" : "=l"(r) : "f"(v.x), "f"(v.y));
    return r;
}
__device__ __forceinline__ void fma2(unsigned long long& d, unsigned long long a,
                                     unsigned long long b) {
    asm("fma.rn.f32x2 %0, %1, %2, %0;" : "+l"(d) : "l"(a), "l"(b));
}
__device__ __forceinline__ float unpk_sum(unsigned long long v) {
    float lo, hi;
    asm("mov.b64 {%0, %1}, %2;" : "=f"(lo), "=f"(hi) : "l"(v));
    return lo + hi;
}

// branchless fast tanh: MUFU EX2 + MUFU RCP, no libm branches. |err| ~1e-6.
__device__ __forceinline__ float tanh_b(float x) {
    float e = __expf(-2.0f * fabsf(x));
    float r = __fdividef(1.0f - e, 1.0f + e);
    return copysignf(r, x);
}

// per-channel kernel value (recompute; used by prep block 0 for ntap scan)
__device__ __forceinline__ float alpha_k(float u, float delta, float tau, float w,
                                         float sgn) {
    float t = fmaxf(u - expf(delta), 0.f);
    float tt = t / expf(tau);
    return sgn * tt * expf(-tt) * expf(w);
}

// ---------------- K0: prep (grid-parallel) ----------------
__global__ void prep_kernel(const float* __restrict__ C_den,
                            const float* __restrict__ Cse,
                            const float* __restrict__ Csi,
                            const float* __restrict__ Tau,
                            const float* __restrict__ Delta,
                            const float* __restrict__ Wsyn,
                            const float* __restrict__ Wsub,
                            const float* __restrict__ Whist,
                            const float* __restrict__ TauOut,
                            const float* __restrict__ Wout,
                            float* __restrict__ d_out, int out_size) {
    const int gtid = blockIdx.x * blockDim.x + threadIdx.x;
    const int gsz  = gridDim.x * blockDim.x;

    // one-hot column -> (subunit, weight)
    for (int e = gtid; e < EE; e += gsz) {
        int s0 = 0; float w = 0.f;
        for (int s = 0; s < SUB; s++) {
            float c = Cse[s * EE + e];
            if (c != 0.f) { s0 = s; w = c; }
        }
        g_lut_e[e] = make_float2(w, __int_as_float(s0));
    }
    for (int e = gtid; e < EI; e += gsz) {
        int s0 = 0; float w = 0.f;
        for (int s = 0; s < SUB; s++) {
            float c = Csi[s * EI + e];
            if (c != 0.f) { s0 = s; w = c; }
        }
        g_lut_i[e] = make_float2(w, __int_as_float(s0));
    }

    // alpha kernels (e/i) + out_filters rows
    for (int idx = gtid; idx < SUB * TAPS; idx += gsz) {
        const int s = idx / TAPS, u = idx % TAPS;
        const float tf = (float)u;
        float ek = alpha_k(tf, Delta[s * 2 + 0], Tau[s * 2 + 0], Wsyn[s * 2 + 0],  1.f);
        float ik = alpha_k(tf, Delta[s * 2 + 1], Tau[s * 2 + 1], Wsyn[s * 2 + 1], -1.f);
        g_ek[idx] = ek;
        g_ik[idx] = ik;
        const int base = 2 * T_DATA;
        if (base + idx < out_size)              d_out[base + idx] = ek;
        if (base + SUB * TAPS + idx < out_size) d_out[base + SUB * TAPS + idx] = ik;
    }

    // history kernel from raised-cosine basis
    for (int u = gtid; u < TAPS; u += gsz) {
        const float raw = 4.0f * logf((float)u + 1.0f);
        const float pi_f    = 3.14159274101257324f;
        const float half_pi = 1.57079637050628662f;
        float hk = 0.f;
        for (int n = 0; n < NCOS; n++) {
            float phi = half_pi * (float)n;
            float b = 0.f;
            if (raw >= phi - pi_f && raw <= phi + pi_f)
                b = 0.5f * cosf(raw - phi) + 0.5f;
            hk -= expf(Whist[n]) * b;
        }
        g_hk[u] = hk;
        const int base = 2 * T_DATA + 2 * SUB * TAPS;
        if (base + u < out_size) d_out[base + u] = hk;
    }

    // output alpha kernel
    for (int u = gtid; u < TAPS; u += gsz) {
        float tto = (float)u / expf(TauOut[0]);
        g_ok[u] = tto * expf(-tto) * expf(Wout[0]);
    }

    // per-node children (binary dendrite tree: <=2 children, larger index)
    if (gtid < SUB) {
        const int i = gtid;
        int c0 = 0, c1 = 0; float w0 = 0.f, w1 = 0.f; int cnt = 0;
        for (int j = i + 1; j < SUB; j++) {
            float c = C_den[i * SUB + j];
            if (c != 0.f) {
                float w = c * expf(Wsub[j]);
                if (cnt == 0) { c0 = j; w0 = w; }
                else          { c1 = j; w1 = w; }
                cnt++;
            }
        }
        g_chn[i * 2 + 0] = c0;  g_chw[i * 2 + 0] = w0;
        g_chn[i * 2 + 1] = c1;  g_chw[i * 2 + 1] = w1;
    }

    // ---- adaptive tap counts (block 0 only; recompute kernels into smem so
    //      there is no cross-block dependency on g_ek/g_ik/g_hk) ----
    if (blockIdx.x == 0) {
        __shared__ float sk[(SUB + 1) * TAPS];  // |e|+|i| combined per channel; ch32 = |hk|
        const int tid = threadIdx.x;
        for (int idx = tid; idx < SUB * TAPS; idx += blockDim.x) {
            const int s = idx / TAPS, u = idx % TAPS;
            const float tf = (float)u;
            float ek = alpha_k(tf, Delta[s * 2 + 0], Tau[s * 2 + 0], Wsyn[s * 2 + 0], 1.f);
            float ik = alpha_k(tf, Delta[s * 2 + 1], Tau[s * 2 + 1], Wsyn[s * 2 + 1], 1.f);
            sk[idx] = fabsf(ek) + fabsf(ik);
        }
        for (int u = tid; u < TAPS; u += blockDim.x) {
            const float raw = 4.0f * logf((float)u + 1.0f);
            const float pi_f    = 3.14159274101257324f;
            const float half_pi = 1.57079637050628662f;
            float hk = 0.f;
            for (int n = 0; n < NCOS; n++) {
                float phi = half_pi * (float)n;
                float b = 0.f;
                if (raw >= phi - pi_f && raw <= phi + pi_f)
                    b = 0.5f * cosf(raw - phi) + 0.5f;
                hk -= expf(Whist[n]) * b;
            }
            sk[SUB * TAPS + u] = fabsf(hk);
        }
        __syncthreads();
        if (tid < SUB + 1) {
            const float* k = sk + tid * TAPS;
            float mx = 0.f;
            for (int u = 0; u < TAPS; u++) mx = fmaxf(mx, k[u]);
            const float thr = mx * 1e-9f;
            int last = 0;
            for (int u = 0; u < TAPS; u++)
                if (k[u] > thr) last = u;
            int U = ((last + 8) / 8) * 8;     // >= last+1, multiple of 8
            if (U < 8) U = 8;
            if (U > TAPS) U = TAPS;
            g_ntap[tid] = U;
        }
    }
}

// ---------------- K1: spike projection (warp-per-row, no div/mod) ----------------
#define PBT 16  // timesteps per block
__global__ void proj_kernel(const float* __restrict__ Se, const float* __restrict__ Si) {
    __shared__ float acc_e[PBT][SUB + 1];
    __shared__ float acc_i[PBT][SUB + 1];
    const int tid  = threadIdx.x;
    const int wid  = tid >> 5;
    const int lane = tid & 31;
    for (int i = tid; i < PBT * (SUB + 1); i += 256) {
        (&acc_e[0][0])[i] = 0.f;
        (&acc_i[0][0])[i] = 0.f;
    }
    __syncthreads();

    const int t0 = blockIdx.x * PBT;
    const float4* Se4 = reinterpret_cast<const float4*>(Se);
    const float4* Si4 = reinterpret_cast<const float4*>(Si);
    const int EROW = EE / 4;  // 500
    const int IROW = EI / 4;  // 100

    #pragma unroll
    for (int rr = 0; rr < 2; rr++) {
        const int tl = wid * 2 + rr;
        const float4* rowE = Se4 + (size_t)(t0 + tl) * EROW;
        float* accE = acc_e[tl];
        #pragma unroll 4
        for (int c4 = lane; c4 < EROW; c4 += 32) {
            const float4 v = rowE[c4];
            if (v.x != 0.f) { float2 p = g_lut_e[c4 * 4 + 0]; atomicAdd(&accE[__float_as_int(p.y)], v.x * p.x); }
            if (v.y != 0.f) { float2 p = g_lut_e[c4 * 4 + 1]; atomicAdd(&accE[__float_as_int(p.y)], v.y * p.x); }
            if (v.z != 0.f) { float2 p = g_lut_e[c4 * 4 + 2]; atomicAdd(&accE[__float_as_int(p.y)], v.z * p.x); }
            if (v.w != 0.f) { float2 p = g_lut_e[c4 * 4 + 3]; atomicAdd(&accE[__float_as_int(p.y)], v.w * p.x); }
        }
        const float4* rowI = Si4 + (size_t)(t0 + tl) * IROW;
        float* accI = acc_i[tl];
        #pragma unroll
        for (int c4 = lane; c4 < IROW; c4 += 32) {
            const float4 v = rowI[c4];
            if (v.x != 0.f) { float2 p = g_lut_i[c4 * 4 + 0]; atomicAdd(&accI[__float_as_int(p.y)], v.x * p.x); }
            if (v.y != 0.f) { float2 p = g_lut_i[c4 * 4 + 1]; atomicAdd(&accI[__float_as_int(p.y)], v.y * p.x); }
            if (v.z != 0.f) { float2 p = g_lut_i[c4 * 4 + 2]; atomicAdd(&accI[__float_as_int(p.y)], v.z * p.x); }
            if (v.w != 0.f) { float2 p = g_lut_i[c4 * 4 + 3]; atomicAdd(&accI[__float_as_int(p.y)], v.w * p.x); }
        }
    }
    __syncthreads();

    for (int idx = tid; idx < SUB * PBT; idx += 256) {
        const int s = idx / PBT, tl = idx % PBT;
        g_syn_e[s * T_DATA + t0 + tl] = acc_e[tl][s];
        g_syn_i[s * T_DATA + t0 + tl] = acc_i[tl][s];
    }
}

// ---------------- K2: 33-ch causal conv, ADAPTIVE tap count ----------
__global__ void conv_kernel(const float* __restrict__ Z) {
    __shared__ float2 sig[PX(CBT + TAPS - 1) + 2];
    __shared__ float2 kk[TAPS];
    const int ch  = blockIdx.y;
    const int t0  = blockIdx.x * CBT;
    const int tid = threadIdx.x;
    const bool has_i = (ch < SUB);

    const float* pe = has_i ? (g_syn_e + ch * T_DATA) : Z;
    const float* pi = has_i ? (g_syn_i + ch * T_DATA) : nullptr;
    const float* ke = has_i ? (g_ek + ch * TAPS) : g_hk;
    const float* ki = has_i ? (g_ik + ch * TAPS) : nullptr;
    const int ntap = g_ntap[ch];   // multiple of 8, in [8, 200]

    for (int i = tid; i < CBT + TAPS; i += 256) {
        const int t = t0 - TAPS + i;
        const bool ok = (t >= 0) && (t < T_DATA);
        float a = ok ? pe[t] : 0.f;
        float b = (ok && has_i) ? pi[t] : 0.f;
        sig[PX(i)] = make_float2(a, b);
    }
    for (int u = tid; u < TAPS; u += 256)
        kk[u] = make_float2(ke[u], has_i ? ki[u] : 0.f);
    __syncthreads();

    const int base = tid * 8;
    unsigned long long acc[8];
    unsigned long long w[8];
    #pragma unroll
    for (int r = 0; r < 8; r++) acc[r] = 0ull;
    #pragma unroll
    for (int r = 0; r < 8; r++) w[(7 + r) & 7] = pk2(sig[PX(base + 199 + r)]);

    for (int g = 0; g < ntap; g += 8) {
        #pragma unroll
        for (int c = 0; c < 8; c++) {
            const int u = g + c;
            if (u > 0) w[(7 - c) & 7] = pk2(sig[PX(base + 199 - u)]);
            const unsigned long long k2 = pk2(kk[u]);
            #pragma unroll
            for (int r = 0; r < 8; r++)
                fma2(acc[r], k2, w[(7 - c + r) & 7]);
        }
    }

    #pragma unroll
    for (int r = 0; r < 8; r++) {
        const int t = t0 + base + r;
        if (t < T_DATA) g_syn[ch * T_DATA + t] = unpk_sum(acc[r]);
    }
}

// ---------------- K3: tree walk, 2 samples/thread, 128-thr blocks (all SMs) ------
__global__ void tree_kernel(const float* __restrict__ Theta,
                            float* __restrict__ d_out, int out_size) {
    __shared__ float th[SUB];
    __shared__ int   chn[SUB * 2];
    __shared__ float chw[SUB * 2];
    const int tid = threadIdx.x;
    if (tid < SUB) th[tid] = Theta[tid];
    if (tid < SUB * 2) { chn[tid] = g_chn[tid]; chw[tid] = g_chw[tid]; }
    __syncthreads();

    const int gid = blockIdx.x * 128 + tid;   // pair index
    const int t0  = gid * 2;
    if (t0 >= T_DATA) return;

    float2 v[SUB + 1];
    const float2* syn2 = reinterpret_cast<const float2*>(g_syn);
    #pragma unroll
    for (int s = 0; s <= SUB; s++) v[s] = syn2[s * (T_DATA / 2) + gid];

    #define TSTEP(idx) {                                                      \
        const int   c0 = chn[2*(idx)],   c1 = chn[2*(idx)+1];                 \
        const float w0 = chw[2*(idx)],   w1 = chw[2*(idx)+1];                 \
        float a0 = v[idx].x + th[idx];                                        \
        float a1 = v[idx].y + th[idx];                                        \
        a0 = fmaf(w0, v[c0].x, a0); a1 = fmaf(w0, v[c0].y, a1);               \
        a0 = fmaf(w1, v[c1].x, a0); a1 = fmaf(w1, v[c1].y, a1);               \
        v[idx].x = tanh_b(a0);      v[idx].y = tanh_b(a1); }
    #pragma unroll
    for (int i = 16; i < 32; i++) TSTEP(i)
    #pragma unroll
    for (int i = 8; i < 16; i++) TSTEP(i)
    #pragma unroll
    for (int i = 4; i < 8; i++) TSTEP(i)
    #pragma unroll
    for (int i = 2; i < 4; i++) TSTEP(i)
    TSTEP(1)
    #undef TSTEP

    const int   c0 = chn[0],  c1 = chn[1];
    const float w0 = chw[0],  w1 = chw[1];
    float z0 = v[SUB].x + v[0].x + th[0];
    float z1 = v[SUB].y + v[0].y + th[0];
    z0 = fmaf(w0, v[c0].x, z0); z1 = fmaf(w0, v[c0].y, z1);
    z0 = fmaf(w1, v[c1].x, z0); z1 = fmaf(w1, v[c1].y, z1);

    float2 zo = make_float2(z0 > 0.f ? 1.f : 0.f, z1 > 0.f ? 1.f : 0.f);
    reinterpret_cast<float2*>(g_zout)[gid] = zo;
    if (T_DATA + t0     < out_size) d_out[T_DATA + t0]     = zo.x;
    if (T_DATA + t0 + 1 < out_size) d_out[T_DATA + t0 + 1] = zo.y;
}

// ---------------- K4: output alpha-kernel conv of Z_out -> V_out ------------------
__global__ void vconv_kernel(float* __restrict__ d_out, int out_size) {
    __shared__ float sig[VBT + TAPS];
    __shared__ float kern[TAPS];
    const int t0  = blockIdx.x * VBT;
    const int tid = threadIdx.x;
    for (int i = tid; i < VBT + TAPS; i += 256) {
        const int t = t0 - TAPS + i;
        sig[i] = (t >= 0 && t < T_DATA) ? g_zout[t] : 0.f;
    }
    for (int u = tid; u < TAPS; u += 256) kern[u] = g_ok[u];
    __syncthreads();

    float a0 = 0.f, a1 = 0.f;
    for (int u = 0; u < TAPS; u++) {
        const float k = kern[u];
        a0 = fmaf(k, sig[tid + 199 - u], a0);
        a1 = fmaf(k, sig[tid + 256 + 199 - u], a1);
    }
    int t = t0 + tid;
    if (t < T_DATA && t < out_size) d_out[t] = a0;
    t += 256;
    if (t < T_DATA && t < out_size) d_out[t] = a1;
}

// ---------------- launch ----------------
extern "C" void kernel_launch(void* const* d_in, const int* in_sizes, int n_in,
                              void* d_out, int out_size) {
    const float* S_e    = (const float*)d_in[0];
    const float* S_i    = (const float*)d_in[1];
    const float* Z      = (const float*)d_in[2];
    const float* C_den  = (const float*)d_in[3];
    const float* Cse    = (const float*)d_in[4];
    const float* Csi    = (const float*)d_in[5];
    const float* Tau    = (const float*)d_in[6];
    const float* Delta  = (const float*)d_in[7];
    const float* Wsyn   = (const float*)d_in[8];
    const float* Wsub   = (const float*)d_in[9];
    const float* Whist  = (const float*)d_in[10];
    const float* Theta  = (const float*)d_in[11];
    const float* TauOut = (const float*)d_in[12];
    const float* Wout   = (const float*)d_in[13];
    float* out = (float*)d_out;

    prep_kernel<<<64, 256>>>(C_den, Cse, Csi, Tau, Delta, Wsyn, Wsub, Whist,
                             TauOut, Wout, out, out_size);
    proj_kernel<<<T_DATA / PBT, 256>>>(S_e, S_i);
    const int ctiles = (T_DATA + CBT - 1) / CBT;  // 20
    conv_kernel<<<dim3(ctiles, SUB + 1), 256>>>(Z);
    tree_kernel<<<(T_DATA / 2 + 127) / 128, 128>>>(Theta, out, out_size);  // 157 blocks
    vconv_kernel<<<(T_DATA + VBT - 1) / VBT, 256>>>(out, out_size);
}

// round 12
// speedup vs baseline: 1.5265x; 1.1082x over previous
#include <cuda_runtime.h>
#include <math.h>

#define T_DATA 40000
#define SUB    32
#define EE     2000
#define EI     400
#define TAPS   200
#define NCOS   17
#define CBT    2048   // conv tile (outputs per block), 256 thr * 8
#define VBT    512    // vconv tile

// padded smem index for conv: conflict-free LDS.64
#define PX(i) ((i) + ((i) >> 3))

// ---------------- device scratch (no allocations allowed) ----------------
__device__ float  g_syn_e[SUB * T_DATA];
__device__ float  g_syn_i[SUB * T_DATA];
__device__ float  g_syn[(SUB + 1) * T_DATA];   // ch 0..31 subunit drive, ch 32 = hist_filt
__device__ float  g_zout[T_DATA];
__device__ float  g_ek[SUB * TAPS];
__device__ float  g_ik[SUB * TAPS];
__device__ float  g_hk[TAPS];
__device__ float  g_ok[TAPS];
__device__ int    g_ntap[SUB + 1];             // adaptive per-channel tap count (mult of 8)
__device__ float  g_cwj[SUB + 1];              // weight for child j (binary tree), [32]=0
__device__ float2 g_lut_e[EE];                 // (weight, bitcast subunit*4 byte-offset)
__device__ float2 g_lut_i[EI];

// ---------------- f32x2 helpers (sm_103a packed fp32) ----------------
__device__ __forceinline__ unsigned long long pk2(float2 v) {
    unsigned long long r;
    asm("mov.b64 %0, {%1, %2};" : "=l"(r) : "f"(v.x), "f"(v.y));
    return r;
}
__device__ __forceinline__ void fma2(unsigned long long& d, unsigned long long a,
                                     unsigned long long b) {
    asm("fma.rn.f32x2 %0, %1, %2, %0;" : "+l"(d) : "l"(a), "l"(b));
}
__device__ __forceinline__ float unpk_sum(unsigned long long v) {
    float lo, hi;
    asm("mov.b64 {%0, %1}, %2;" : "=f"(lo), "=f"(hi) : "l"(v));
    return lo + hi;
}

// branchless fast tanh: MUFU EX2 + MUFU RCP, no libm branches. |err| ~1e-6.
__device__ __forceinline__ float tanh_b(float x) {
    float e = __expf(-2.0f * fabsf(x));
    float r = __fdividef(1.0f - e, 1.0f + e);
    return copysignf(r, x);
}

// predicated shared-mem reduction: NO BSSY/BSYNC (ptxas won't emit this from C++)
__device__ __forceinline__ void red_if(unsigned accBase, float2 p, float v) {
    unsigned addr = accBase + (unsigned)__float_as_int(p.y);  // p.y = byte offset
    asm volatile(
        "{\n\t"
        ".reg .pred q;\n\t"
        "setp.ne.f32 q, %0, 0f00000000;\n\t"
        "@q red.shared.add.f32 [%1], %2;\n\t"
        "}"
        :: "f"(v), "r"(addr), "f"(v * p.x) : "memory");
}

__device__ __forceinline__ float alpha_k(float u, float delta, float tau, float w,
                                         float sgn) {
    float t = fmaxf(u - expf(delta), 0.f);
    float tt = t / expf(tau);
    return sgn * tt * expf(-tt) * expf(w);
}

// ---------------- K0: prep (grid-parallel) ----------------
__global__ void prep_kernel(const float* __restrict__ C_den,
                            const float* __restrict__ Cse,
                            const float* __restrict__ Csi,
                            const float* __restrict__ Tau,
                            const float* __restrict__ Delta,
                            const float* __restrict__ Wsyn,
                            const float* __restrict__ Wsub,
                            const float* __restrict__ Whist,
                            const float* __restrict__ TauOut,
                            const float* __restrict__ Wout,
                            float* __restrict__ d_out, int out_size) {
    const int gtid = blockIdx.x * blockDim.x + threadIdx.x;
    const int gsz  = gridDim.x * blockDim.x;

    // one-hot column -> (weight, byte offset of subunit)
    for (int e = gtid; e < EE; e += gsz) {
        int s0 = 0; float w = 0.f;
        for (int s = 0; s < SUB; s++) {
            float c = Cse[s * EE + e];
            if (c != 0.f) { s0 = s; w = c; }
        }
        g_lut_e[e] = make_float2(w, __int_as_float(s0 * 4));
    }
    for (int e = gtid; e < EI; e += gsz) {
        int s0 = 0; float w = 0.f;
        for (int s = 0; s < SUB; s++) {
            float c = Csi[s * EI + e];
            if (c != 0.f) { s0 = s; w = c; }
        }
        g_lut_i[e] = make_float2(w, __int_as_float(s0 * 4));
    }

    // alpha kernels (e/i) + out_filters rows
    for (int idx = gtid; idx < SUB * TAPS; idx += gsz) {
        const int s = idx / TAPS, u = idx % TAPS;
        const float tf = (float)u;
        float ek = alpha_k(tf, Delta[s * 2 + 0], Tau[s * 2 + 0], Wsyn[s * 2 + 0],  1.f);
        float ik = alpha_k(tf, Delta[s * 2 + 1], Tau[s * 2 + 1], Wsyn[s * 2 + 1], -1.f);
        g_ek[idx] = ek;
        g_ik[idx] = ik;
        const int base = 2 * T_DATA;
        if (base + idx < out_size)              d_out[base + idx] = ek;
        if (base + SUB * TAPS + idx < out_size) d_out[base + SUB * TAPS + idx] = ik;
    }

    // history kernel from raised-cosine basis
    for (int u = gtid; u < TAPS; u += gsz) {
        const float raw = 4.0f * logf((float)u + 1.0f);
        const float pi_f    = 3.14159274101257324f;
        const float half_pi = 1.57079637050628662f;
        float hk = 0.f;
        for (int n = 0; n < NCOS; n++) {
            float phi = half_pi * (float)n;
            float b = 0.f;
            if (raw >= phi - pi_f && raw <= phi + pi_f)
                b = 0.5f * cosf(raw - phi) + 0.5f;
            hk -= expf(Whist[n]) * b;
        }
        g_hk[u] = hk;
        const int base = 2 * T_DATA + 2 * SUB * TAPS;
        if (base + u < out_size) d_out[base + u] = hk;
    }

    // output alpha kernel
    for (int u = gtid; u < TAPS; u += gsz) {
        float tto = (float)u / expf(TauOut[0]);
        g_ok[u] = tto * expf(-tto) * expf(Wout[0]);
    }

    // binary-tree child weights: child j of parent (j-1)/2
    if (gtid >= 1 && gtid < SUB)
        g_cwj[gtid] = C_den[((gtid - 1) >> 1) * SUB + gtid] * expf(Wsub[gtid]);
    if (gtid == 0) { g_cwj[0] = 0.f; g_cwj[SUB] = 0.f; }

    // adaptive tap counts (block 0 only; recompute into smem — no cross-block dep)
    if (blockIdx.x == 0) {
        __shared__ float sk[(SUB + 1) * TAPS];
        const int tid = threadIdx.x;
        for (int idx = tid; idx < SUB * TAPS; idx += blockDim.x) {
            const int s = idx / TAPS, u = idx % TAPS;
            const float tf = (float)u;
            float ek = alpha_k(tf, Delta[s * 2 + 0], Tau[s * 2 + 0], Wsyn[s * 2 + 0], 1.f);
            float ik = alpha_k(tf, Delta[s * 2 + 1], Tau[s * 2 + 1], Wsyn[s * 2 + 1], 1.f);
            sk[idx] = fabsf(ek) + fabsf(ik);
        }
        for (int u = tid; u < TAPS; u += blockDim.x) {
            const float raw = 4.0f * logf((float)u + 1.0f);
            const float pi_f    = 3.14159274101257324f;
            const float half_pi = 1.57079637050628662f;
            float hk = 0.f;
            for (int n = 0; n < NCOS; n++) {
                float phi = half_pi * (float)n;
                float b = 0.f;
                if (raw >= phi - pi_f && raw <= phi + pi_f)
                    b = 0.5f * cosf(raw - phi) + 0.5f;
                hk -= expf(Whist[n]) * b;
            }
            sk[SUB * TAPS + u] = fabsf(hk);
        }
        __syncthreads();
        if (tid < SUB + 1) {
            const float* k = sk + tid * TAPS;
            float mx = 0.f;
            for (int u = 0; u < TAPS; u++) mx = fmaxf(mx, k[u]);
            const float thr = mx * 1e-9f;
            int last = 0;
            for (int u = 0; u < TAPS; u++)
                if (k[u] > thr) last = u;
            int U = ((last + 8) / 8) * 8;
            if (U < 8) U = 8;
            if (U > TAPS) U = TAPS;
            g_ntap[tid] = U;
        }
    }
}

// ---------------- K1: spike projection — branch-free predicated RED ----------------
#define PBT 16  // timesteps per block
#define EROW (EE / 4)
#define IROW (EI / 4)
__global__ void proj_kernel(const float* __restrict__ Se, const float* __restrict__ Si) {
    __shared__ float2 lutE[4][EROW];   // component-split: conflict-free LDS.64
    __shared__ float2 lutI[4][IROW];
    __shared__ float  acc_e[PBT][SUB + 1];
    __shared__ float  acc_i[PBT][SUB + 1];
    const int tid  = threadIdx.x;
    const int wid  = tid >> 5;
    const int lane = tid & 31;

    for (int c = tid; c < EE; c += 256) lutE[c & 3][c >> 2] = g_lut_e[c];
    for (int c = tid; c < EI; c += 256) lutI[c & 3][c >> 2] = g_lut_i[c];
    for (int i = tid; i < PBT * (SUB + 1); i += 256) {
        (&acc_e[0][0])[i] = 0.f;
        (&acc_i[0][0])[i] = 0.f;
    }
    __syncthreads();

    const int t0 = blockIdx.x * PBT;
    const float4* Se4 = reinterpret_cast<const float4*>(Se);
    const float4* Si4 = reinterpret_cast<const float4*>(Si);

    #pragma unroll
    for (int rr = 0; rr < 2; rr++) {
        const int tl = wid * 2 + rr;
        const float4* rowE = Se4 + (size_t)(t0 + tl) * EROW;
        const unsigned accE = (unsigned)__cvta_generic_to_shared(acc_e[tl]);
        #pragma unroll 4
        for (int c4 = lane; c4 < EROW; c4 += 32) {
            const float4 v = rowE[c4];
            red_if(accE, lutE[0][c4], v.x);
            red_if(accE, lutE[1][c4], v.y);
            red_if(accE, lutE[2][c4], v.z);
            red_if(accE, lutE[3][c4], v.w);
        }
        const float4* rowI = Si4 + (size_t)(t0 + tl) * IROW;
        const unsigned accI = (unsigned)__cvta_generic_to_shared(acc_i[tl]);
        #pragma unroll
        for (int c4 = lane; c4 < IROW; c4 += 32) {
            const float4 v = rowI[c4];
            red_if(accI, lutI[0][c4], v.x);
            red_if(accI, lutI[1][c4], v.y);
            red_if(accI, lutI[2][c4], v.z);
            red_if(accI, lutI[3][c4], v.w);
        }
    }
    __syncthreads();

    for (int idx = tid; idx < SUB * PBT; idx += 256) {
        const int s = idx / PBT, tl = idx % PBT;
        g_syn_e[s * T_DATA + t0 + tl] = acc_e[tl][s];
        g_syn_i[s * T_DATA + t0 + tl] = acc_i[tl][s];
    }
}

// ---------------- K2: 33-ch causal conv, adaptive tap count ----------
__global__ void conv_kernel(const float* __restrict__ Z) {
    __shared__ float2 sig[PX(CBT + TAPS - 1) + 2];
    __shared__ float2 kk[TAPS];
    const int ch  = blockIdx.y;
    const int t0  = blockIdx.x * CBT;
    const int tid = threadIdx.x;
    const bool has_i = (ch < SUB);

    const float* pe = has_i ? (g_syn_e + ch * T_DATA) : Z;
    const float* pi = has_i ? (g_syn_i + ch * T_DATA) : nullptr;
    const float* ke = has_i ? (g_ek + ch * TAPS) : g_hk;
    const float* ki = has_i ? (g_ik + ch * TAPS) : nullptr;
    const int ntap = g_ntap[ch];

    for (int i = tid; i < CBT + TAPS; i += 256) {
        const int t = t0 - TAPS + i;
        const bool ok = (t >= 0) && (t < T_DATA);
        float a = ok ? pe[t] : 0.f;
        float b = (ok && has_i) ? pi[t] : 0.f;
        sig[PX(i)] = make_float2(a, b);
    }
    for (int u = tid; u < TAPS; u += 256)
        kk[u] = make_float2(ke[u], has_i ? ki[u] : 0.f);
    __syncthreads();

    const int base = tid * 8;
    unsigned long long acc[8];
    unsigned long long w[8];
    #pragma unroll
    for (int r = 0; r < 8; r++) acc[r] = 0ull;
    #pragma unroll
    for (int r = 0; r < 8; r++) w[(7 + r) & 7] = pk2(sig[PX(base + 199 + r)]);

    for (int g = 0; g < ntap; g += 8) {
        #pragma unroll
        for (int c = 0; c < 8; c++) {
            const int u = g + c;
            if (u > 0) w[(7 - c) & 7] = pk2(sig[PX(base + 199 - u)]);
            const unsigned long long k2 = pk2(kk[u]);
            #pragma unroll
            for (int r = 0; r < 8; r++)
                fma2(acc[r], k2, w[(7 - c + r) & 7]);
        }
    }

    #pragma unroll
    for (int r = 0; r < 8; r++) {
        const int t = t0 + base + r;
        if (t < T_DATA) g_syn[ch * T_DATA + t] = unpk_sum(acc[r]);
    }
}

// ---------------- K3: tree walk, STATIC topology (register-resident v[]) ---------
__global__ void tree_kernel(const float* __restrict__ Theta,
                            float* __restrict__ d_out, int out_size) {
    __shared__ float th[SUB];
    __shared__ float cw[SUB + 1];      // cw[32] = 0
    const int tid = threadIdx.x;
    if (tid < SUB) th[tid] = Theta[tid];
    if (tid < SUB + 1) cw[tid] = g_cwj[tid];
    __syncthreads();

    const int t = blockIdx.x * 256 + tid;
    if (t >= T_DATA) return;

    float v[SUB + 1];
    #pragma unroll
    for (int s = 0; s < SUB; s++) v[s] = g_syn[s * T_DATA + t];
    v[SUB] = 0.f;
    const float hist = g_syn[SUB * T_DATA + t];

    // leaves (no children)
    #pragma unroll
    for (int i = 16; i < SUB; i++) v[i] = tanh_b(v[i] + th[i]);
    // internal nodes: children 2i+1, 2i+2 (compile-time indices; i=15 uses v[32]=0)
    #pragma unroll
    for (int i = 15; i >= 1; i--) {
        float a = v[i] + th[i];
        a = fmaf(cw[2 * i + 1], v[2 * i + 1], a);
        a = fmaf(cw[2 * i + 2], v[2 * i + 2], a);
        v[i] = tanh_b(a);
    }

    float zin = hist + v[0] + th[0];
    zin = fmaf(cw[1], v[1], zin);
    zin = fmaf(cw[2], v[2], zin);

    const float zo = (zin > 0.f) ? 1.f : 0.f;
    g_zout[t] = zo;
    if (T_DATA + t < out_size) d_out[T_DATA + t] = zo;
}

// ---------------- K4: output alpha-kernel conv of Z_out -> V_out ------------------
__global__ void vconv_kernel(float* __restrict__ d_out, int out_size) {
    __shared__ float sig[VBT + TAPS];
    __shared__ float kern[TAPS];
    const int t0  = blockIdx.x * VBT;
    const int tid = threadIdx.x;
    for (int i = tid; i < VBT + TAPS; i += 256) {
        const int t = t0 - TAPS + i;
        sig[i] = (t >= 0 && t < T_DATA) ? g_zout[t] : 0.f;
    }
    for (int u = tid; u < TAPS; u += 256) kern[u] = g_ok[u];
    __syncthreads();

    float a0 = 0.f, a1 = 0.f;
    for (int u = 0; u < TAPS; u++) {
        const float k = kern[u];
        a0 = fmaf(k, sig[tid + 199 - u], a0);
        a1 = fmaf(k, sig[tid + 256 + 199 - u], a1);
    }
    int t = t0 + tid;
    if (t < T_DATA && t < out_size) d_out[t] = a0;
    t += 256;
    if (t < T_DATA && t < out_size) d_out[t] = a1;
}

// ---------------- launch ----------------
extern "C" void kernel_launch(void* const* d_in, const int* in_sizes, int n_in,
                              void* d_out, int out_size) {
    const float* S_e    = (const float*)d_in[0];
    const float* S_i    = (const float*)d_in[1];
    const float* Z      = (const float*)d_in[2];
    const float* C_den  = (const float*)d_in[3];
    const float* Cse    = (const float*)d_in[4];
    const float* Csi    = (const float*)d_in[5];
    const float* Tau    = (const float*)d_in[6];
    const float* Delta  = (const float*)d_in[7];
    const float* Wsyn   = (const float*)d_in[8];
    const float* Wsub   = (const float*)d_in[9];
    const float* Whist  = (const float*)d_in[10];
    const float* Theta  = (const float*)d_in[11];
    const float* TauOut = (const float*)d_in[12];
    const float* Wout   = (const float*)d_in[13];
    float* out = (float*)d_out;

    prep_kernel<<<64, 256>>>(C_den, Cse, Csi, Tau, Delta, Wsyn, Wsub, Whist,
                             TauOut, Wout, out, out_size);
    proj_kernel<<<T_DATA / PBT, 256>>>(S_e, S_i);
    const int ctiles = (T_DATA + CBT - 1) / CBT;  // 20
    conv_kernel<<<dim3(ctiles, SUB + 1), 256>>>(Z);
    tree_kernel<<<(T_DATA + 255) / 256, 256>>>(Theta, out, out_size);
    vconv_kernel<<<(T_DATA + VBT - 1) / VBT, 256>>>(out, out_size);
}

// round 13
// speedup vs baseline: 1.6944x; 1.1100x over previous
#include <cuda_runtime.h>
#include <math.h>

#define T_DATA 40000
#define SUB    32
#define EE     2000
#define EI     400
#define TAPS   200
#define NCOS   17
#define CBT    2048   // conv tile (outputs per block), 256 thr * 8
#define VBT    512    // vconv tile

// padded smem index for conv: conflict-free LDS.64
#define PX(i) ((i) + ((i) >> 3))

// ---------------- device scratch (no allocations allowed) ----------------
__device__ float  g_syn_e[SUB * T_DATA];
__device__ float  g_syn_i[SUB * T_DATA];
__device__ float  g_syn[(SUB + 1) * T_DATA];   // ch 0..31 subunit drive, ch 32 = hist_filt
__device__ float  g_zout[T_DATA];
__device__ float  g_ek[SUB * TAPS];
__device__ float  g_ik[SUB * TAPS];
__device__ float  g_hk[TAPS];
__device__ float  g_ok[TAPS];
__device__ int    g_ntap[SUB + 1];             // adaptive per-channel tap count (mult of 8)
__device__ float  g_cwj[SUB + 1];              // weight for child j (binary tree), [32]=0
__device__ float2 g_lut_e[EE];                 // (weight, bitcast subunit*4 byte-offset)
__device__ float2 g_lut_i[EI];

// ---------------- f32x2 helpers (sm_103a packed fp32) ----------------
__device__ __forceinline__ unsigned long long pk2(float2 v) {
    unsigned long long r;
    asm("mov.b64 %0, {%1, %2};" : "=l"(r) : "f"(v.x), "f"(v.y));
    return r;
}
__device__ __forceinline__ void fma2(unsigned long long& d, unsigned long long a,
                                     unsigned long long b) {
    asm("fma.rn.f32x2 %0, %1, %2, %0;" : "+l"(d) : "l"(a), "l"(b));
}
__device__ __forceinline__ float unpk_sum(unsigned long long v) {
    float lo, hi;
    asm("mov.b64 {%0, %1}, %2;" : "=f"(lo), "=f"(hi) : "l"(v));
    return lo + hi;
}

// branchless fast tanh: MUFU EX2 + MUFU RCP. |err| ~1e-6.
__device__ __forceinline__ float tanh_b(float x) {
    float e = __expf(-2.0f * fabsf(x));
    float r = __fdividef(1.0f - e, 1.0f + e);
    return copysignf(r, x);
}

// predicated shared-mem reduction: no BSSY/BSYNC
__device__ __forceinline__ void red_if(unsigned accBase, float2 p, float v) {
    unsigned addr = accBase + (unsigned)__float_as_int(p.y);  // p.y = byte offset
    asm volatile(
        "{\n\t"
        ".reg .pred q;\n\t"
        "setp.ne.f32 q, %0, 0f00000000;\n\t"
        "@q red.shared.add.f32 [%1], %2;\n\t"
        "}"
        :: "f"(v), "r"(addr), "f"(v * p.x) : "memory");
}

__device__ __forceinline__ float alpha_k(float u, float delta, float tau, float w,
                                         float sgn) {
    float t = fmaxf(u - expf(delta), 0.f);
    float tt = t / expf(tau);
    return sgn * tt * expf(-tt) * expf(w);
}

// ---------------- K0: prep (grid-parallel) ----------------
__global__ void prep_kernel(const float* __restrict__ C_den,
                            const float* __restrict__ Cse,
                            const float* __restrict__ Csi,
                            const float* __restrict__ Tau,
                            const float* __restrict__ Delta,
                            const float* __restrict__ Wsyn,
                            const float* __restrict__ Wsub,
                            const float* __restrict__ Whist,
                            const float* __restrict__ TauOut,
                            const float* __restrict__ Wout,
                            float* __restrict__ d_out, int out_size) {
    const int gtid = blockIdx.x * blockDim.x + threadIdx.x;
    const int gsz  = gridDim.x * blockDim.x;

    for (int e = gtid; e < EE; e += gsz) {
        int s0 = 0; float w = 0.f;
        for (int s = 0; s < SUB; s++) {
            float c = Cse[s * EE + e];
            if (c != 0.f) { s0 = s; w = c; }
        }
        g_lut_e[e] = make_float2(w, __int_as_float(s0 * 4));
    }
    for (int e = gtid; e < EI; e += gsz) {
        int s0 = 0; float w = 0.f;
        for (int s = 0; s < SUB; s++) {
            float c = Csi[s * EI + e];
            if (c != 0.f) { s0 = s; w = c; }
        }
        g_lut_i[e] = make_float2(w, __int_as_float(s0 * 4));
    }

    for (int idx = gtid; idx < SUB * TAPS; idx += gsz) {
        const int s = idx / TAPS, u = idx % TAPS;
        const float tf = (float)u;
        float ek = alpha_k(tf, Delta[s * 2 + 0], Tau[s * 2 + 0], Wsyn[s * 2 + 0],  1.f);
        float ik = alpha_k(tf, Delta[s * 2 + 1], Tau[s * 2 + 1], Wsyn[s * 2 + 1], -1.f);
        g_ek[idx] = ek;
        g_ik[idx] = ik;
        const int base = 2 * T_DATA;
        if (base + idx < out_size)              d_out[base + idx] = ek;
        if (base + SUB * TAPS + idx < out_size) d_out[base + SUB * TAPS + idx] = ik;
    }

    for (int u = gtid; u < TAPS; u += gsz) {
        const float raw = 4.0f * logf((float)u + 1.0f);
        const float pi_f    = 3.14159274101257324f;
        const float half_pi = 1.57079637050628662f;
        float hk = 0.f;
        for (int n = 0; n < NCOS; n++) {
            float phi = half_pi * (float)n;
            float b = 0.f;
            if (raw >= phi - pi_f && raw <= phi + pi_f)
                b = 0.5f * cosf(raw - phi) + 0.5f;
            hk -= expf(Whist[n]) * b;
        }
        g_hk[u] = hk;
        const int base = 2 * T_DATA + 2 * SUB * TAPS;
        if (base + u < out_size) d_out[base + u] = hk;
    }

    for (int u = gtid; u < TAPS; u += gsz) {
        float tto = (float)u / expf(TauOut[0]);
        g_ok[u] = tto * expf(-tto) * expf(Wout[0]);
    }

    if (gtid >= 1 && gtid < SUB)
        g_cwj[gtid] = C_den[((gtid - 1) >> 1) * SUB + gtid] * expf(Wsub[gtid]);
    if (gtid == 0) { g_cwj[0] = 0.f; g_cwj[SUB] = 0.f; }

    // adaptive tap counts (block 0 only)
    if (blockIdx.x == 0) {
        __shared__ float sk[(SUB + 1) * TAPS];
        const int tid = threadIdx.x;
        for (int idx = tid; idx < SUB * TAPS; idx += blockDim.x) {
            const int s = idx / TAPS, u = idx % TAPS;
            const float tf = (float)u;
            float ek = alpha_k(tf, Delta[s * 2 + 0], Tau[s * 2 + 0], Wsyn[s * 2 + 0], 1.f);
            float ik = alpha_k(tf, Delta[s * 2 + 1], Tau[s * 2 + 1], Wsyn[s * 2 + 1], 1.f);
            sk[idx] = fabsf(ek) + fabsf(ik);
        }
        for (int u = tid; u < TAPS; u += blockDim.x) {
            const float raw = 4.0f * logf((float)u + 1.0f);
            const float pi_f    = 3.14159274101257324f;
            const float half_pi = 1.57079637050628662f;
            float hk = 0.f;
            for (int n = 0; n < NCOS; n++) {
                float phi = half_pi * (float)n;
                float b = 0.f;
                if (raw >= phi - pi_f && raw <= phi + pi_f)
                    b = 0.5f * cosf(raw - phi) + 0.5f;
                hk -= expf(Whist[n]) * b;
            }
            sk[SUB * TAPS + u] = fabsf(hk);
        }
        __syncthreads();
        if (tid < SUB + 1) {
            const float* k = sk + tid * TAPS;
            float mx = 0.f;
            for (int u = 0; u < TAPS; u++) mx = fmaxf(mx, k[u]);
            const float thr = mx * 1e-9f;
            int last = 0;
            for (int u = 0; u < TAPS; u++)
                if (k[u] > thr) last = u;
            int U = ((last + 8) / 8) * 8;
            if (U < 8) U = 8;
            if (U > TAPS) U = TAPS;
            g_ntap[tid] = U;
        }
    }
}

// ---------------- K1: spike projection — double-buffered loads + predicated RED ----
#define PBT 16  // timesteps per block
#define EROW (EE / 4)     // 500
#define IROW (EI / 4)     // 100
#define EITER (EROW / 32 + 1)  // 16 iterations (last partial)
#define IITER (IROW / 32 + 1)  // 4 iterations (last partial)
__global__ void proj_kernel(const float* __restrict__ Se, const float* __restrict__ Si) {
    // LUTs padded to next pow2 so tail-iteration OOB lane indices stay in-bounds
    // (their v is 0 -> red predicated off; value irrelevant)
    __shared__ float2 lutE[4][512];
    __shared__ float2 lutI[4][128];
    __shared__ float  acc_e[PBT][SUB + 1];
    __shared__ float  acc_i[PBT][SUB + 1];
    const int tid  = threadIdx.x;
    const int wid  = tid >> 5;
    const int lane = tid & 31;

    for (int c = tid; c < EE; c += 256) lutE[c & 3][c >> 2] = g_lut_e[c];
    for (int c = tid; c < EI; c += 256) lutI[c & 3][c >> 2] = g_lut_i[c];
    for (int i = tid; i < PBT * (SUB + 1); i += 256) {
        (&acc_e[0][0])[i] = 0.f;
        (&acc_i[0][0])[i] = 0.f;
    }
    __syncthreads();

    const int t0 = blockIdx.x * PBT;
    const float4* Se4 = reinterpret_cast<const float4*>(Se);
    const float4* Si4 = reinterpret_cast<const float4*>(Si);
    const float4 z4 = make_float4(0.f, 0.f, 0.f, 0.f);

    #pragma unroll
    for (int rr = 0; rr < 2; rr++) {
        const int tl = wid * 2 + rr;
        {   // ---- excitatory row: double-buffered, prefetch precedes reds ----
            const float4* rowE = Se4 + (size_t)(t0 + tl) * EROW;
            const unsigned accE = (unsigned)__cvta_generic_to_shared(acc_e[tl]);
            float4 cur = rowE[lane];           // k=0 always valid
            #pragma unroll
            for (int k = 0; k < EITER; k++) {
                const int nidx = lane + 32 * (k + 1);
                float4 nxt = (k + 1 < EITER && nidx < EROW) ? rowE[nidx] : z4;
                const int c4 = lane + 32 * k;  // may exceed EROW on tail: cur==0 then
                red_if(accE, lutE[0][c4], cur.x);
                red_if(accE, lutE[1][c4], cur.y);
                red_if(accE, lutE[2][c4], cur.z);
                red_if(accE, lutE[3][c4], cur.w);
                cur = nxt;
            }
        }
        {   // ---- inhibitory row ----
            const float4* rowI = Si4 + (size_t)(t0 + tl) * IROW;
            const unsigned accI = (unsigned)__cvta_generic_to_shared(acc_i[tl]);
            float4 cur = rowI[lane];           // k=0 always valid
            #pragma unroll
            for (int k = 0; k < IITER; k++) {
                const int nidx = lane + 32 * (k + 1);
                float4 nxt = (k + 1 < IITER && nidx < IROW) ? rowI[nidx] : z4;
                const int c4 = lane + 32 * k;
                red_if(accI, lutI[0][c4], cur.x);
                red_if(accI, lutI[1][c4], cur.y);
                red_if(accI, lutI[2][c4], cur.z);
                red_if(accI, lutI[3][c4], cur.w);
                cur = nxt;
            }
        }
    }
    __syncthreads();

    for (int idx = tid; idx < SUB * PBT; idx += 256) {
        const int s = idx / PBT, tl = idx % PBT;
        g_syn_e[s * T_DATA + t0 + tl] = acc_e[tl][s];
        g_syn_i[s * T_DATA + t0 + tl] = acc_i[tl][s];
    }
}

// ---------------- K2: 33-ch causal conv, adaptive tap count ----------
__global__ void conv_kernel(const float* __restrict__ Z) {
    __shared__ float2 sig[PX(CBT + TAPS - 1) + 2];
    __shared__ float2 kk[TAPS];
    const int ch  = blockIdx.y;
    const int t0  = blockIdx.x * CBT;
    const int tid = threadIdx.x;
    const bool has_i = (ch < SUB);

    const float* pe = has_i ? (g_syn_e + ch * T_DATA) : Z;
    const float* pi = has_i ? (g_syn_i + ch * T_DATA) : nullptr;
    const float* ke = has_i ? (g_ek + ch * TAPS) : g_hk;
    const float* ki = has_i ? (g_ik + ch * TAPS) : nullptr;
    const int ntap = g_ntap[ch];

    for (int i = tid; i < CBT + TAPS; i += 256) {
        const int t = t0 - TAPS + i;
        const bool ok = (t >= 0) && (t < T_DATA);
        float a = ok ? pe[t] : 0.f;
        float b = (ok && has_i) ? pi[t] : 0.f;
        sig[PX(i)] = make_float2(a, b);
    }
    for (int u = tid; u < TAPS; u += 256)
        kk[u] = make_float2(ke[u], has_i ? ki[u] : 0.f);
    __syncthreads();

    const int base = tid * 8;
    unsigned long long acc[8];
    unsigned long long w[8];
    #pragma unroll
    for (int r = 0; r < 8; r++) acc[r] = 0ull;
    #pragma unroll
    for (int r = 0; r < 8; r++) w[(7 + r) & 7] = pk2(sig[PX(base + 199 + r)]);

    for (int g = 0; g < ntap; g += 8) {
        #pragma unroll
        for (int c = 0; c < 8; c++) {
            const int u = g + c;
            if (u > 0) w[(7 - c) & 7] = pk2(sig[PX(base + 199 - u)]);
            const unsigned long long k2 = pk2(kk[u]);
            #pragma unroll
            for (int r = 0; r < 8; r++)
                fma2(acc[r], k2, w[(7 - c + r) & 7]);
        }
    }

    #pragma unroll
    for (int r = 0; r < 8; r++) {
        const int t = t0 + base + r;
        if (t < T_DATA) g_syn[ch * T_DATA + t] = unpk_sum(acc[r]);
    }
}

// ---------------- K3: tree walk — static topology + 2 samples/thread ---------
__global__ void tree_kernel(const float* __restrict__ Theta,
                            float* __restrict__ d_out, int out_size) {
    __shared__ float th[SUB];
    __shared__ float cw[SUB + 1];      // cw[32] = 0
    const int tid = threadIdx.x;
    if (tid < SUB) th[tid] = Theta[tid];
    if (tid < SUB + 1) cw[tid] = g_cwj[tid];
    __syncthreads();

    const int gid = blockIdx.x * 128 + tid;   // sample-pair index
    const int t0  = gid * 2;
    if (t0 >= T_DATA) return;

    float2 v[SUB + 1];
    const float2* syn2 = reinterpret_cast<const float2*>(g_syn);
    #pragma unroll
    for (int s = 0; s < SUB; s++) v[s] = syn2[s * (T_DATA / 2) + gid];
    const float2 hist = syn2[SUB * (T_DATA / 2) + gid];
    v[SUB] = make_float2(0.f, 0.f);

    // leaves 16..31 (no children); both samples interleave for 2x MUFU ILP
    #pragma unroll
    for (int i = 16; i < SUB; i++) {
        v[i].x = tanh_b(v[i].x + th[i]);
        v[i].y = tanh_b(v[i].y + th[i]);
    }
    // internal 15..1: children 2i+1, 2i+2 (compile-time; i=15 uses v[32]=0, cw[32]=0)
    #pragma unroll
    for (int i = 15; i >= 1; i--) {
        const float wl = cw[2 * i + 1], wr = cw[2 * i + 2];
        float a0 = v[i].x + th[i];
        float a1 = v[i].y + th[i];
        a0 = fmaf(wl, v[2 * i + 1].x, a0); a1 = fmaf(wl, v[2 * i + 1].y, a1);
        a0 = fmaf(wr, v[2 * i + 2].x, a0); a1 = fmaf(wr, v[2 * i + 2].y, a1);
        v[i].x = tanh_b(a0);
        v[i].y = tanh_b(a1);
    }

    float z0 = hist.x + v[0].x + th[0];
    float z1 = hist.y + v[0].y + th[0];
    z0 = fmaf(cw[1], v[1].x, z0); z1 = fmaf(cw[1], v[1].y, z1);
    z0 = fmaf(cw[2], v[2].x, z0); z1 = fmaf(cw[2], v[2].y, z1);

    float2 zo = make_float2(z0 > 0.f ? 1.f : 0.f, z1 > 0.f ? 1.f : 0.f);
    reinterpret_cast<float2*>(g_zout)[gid] = zo;
    if (T_DATA + t0     < out_size) d_out[T_DATA + t0]     = zo.x;
    if (T_DATA + t0 + 1 < out_size) d_out[T_DATA + t0 + 1] = zo.y;
}

// ---------------- K4: output alpha-kernel conv of Z_out -> V_out ------------------
__global__ void vconv_kernel(float* __restrict__ d_out, int out_size) {
    __shared__ float sig[VBT + TAPS];
    __shared__ float kern[TAPS];
    const int t0  = blockIdx.x * VBT;
    const int tid = threadIdx.x;
    for (int i = tid; i < VBT + TAPS; i += 256) {
        const int t = t0 - TAPS + i;
        sig[i] = (t >= 0 && t < T_DATA) ? g_zout[t] : 0.f;
    }
    for (int u = tid; u < TAPS; u += 256) kern[u] = g_ok[u];
    __syncthreads();

    float a0 = 0.f, a1 = 0.f;
    for (int u = 0; u < TAPS; u++) {
        const float k = kern[u];
        a0 = fmaf(k, sig[tid + 199 - u], a0);
        a1 = fmaf(k, sig[tid + 256 + 199 - u], a1);
    }
    int t = t0 + tid;
    if (t < T_DATA && t < out_size) d_out[t] = a0;
    t += 256;
    if (t < T_DATA && t < out_size) d_out[t] = a1;
}

// ---------------- launch ----------------
extern "C" void kernel_launch(void* const* d_in, const int* in_sizes, int n_in,
                              void* d_out, int out_size) {
    const float* S_e    = (const float*)d_in[0];
    const float* S_i    = (const float*)d_in[1];
    const float* Z      = (const float*)d_in[2];
    const float* C_den  = (const float*)d_in[3];
    const float* Cse    = (const float*)d_in[4];
    const float* Csi    = (const float*)d_in[5];
    const float* Tau    = (const float*)d_in[6];
    const float* Delta  = (const float*)d_in[7];
    const float* Wsyn   = (const float*)d_in[8];
    const float* Wsub   = (const float*)d_in[9];
    const float* Whist  = (const float*)d_in[10];
    const float* Theta  = (const float*)d_in[11];
    const float* TauOut = (const float*)d_in[12];
    const float* Wout   = (const float*)d_in[13];
    float* out = (float*)d_out;

    prep_kernel<<<64, 256>>>(C_den, Cse, Csi, Tau, Delta, Wsyn, Wsub, Whist,
                             TauOut, Wout, out, out_size);
    proj_kernel<<<T_DATA / PBT, 256>>>(S_e, S_i);
    const int ctiles = (T_DATA + CBT - 1) / CBT;  // 20
    conv_kernel<<<dim3(ctiles, SUB + 1), 256>>>(Z);
    tree_kernel<<<(T_DATA / 2 + 127) / 128, 128>>>(Theta, out, out_size);  // 157 blocks
    vconv_kernel<<<(T_DATA + VBT - 1) / VBT, 256>>>(out, out_size);
}